// round 1
// baseline (speedup 1.0000x reference)
#include <cuda_runtime.h>

#define L_SEQ 96
#define N_V   207
#define N_B   4
#define N_C   512          // H*E channels
#define TOPK  4
#define CHUNK_C 32         // channels per smem chunk (16 float2 pairs)
#define N_CHUNK (N_C / CHUNK_C)   // 16
#define TPB_A 192          // 12 lag-groups * 16 channel-pairs

// scratch (device globals: no allocation allowed)
__device__ float g_mv[N_B * N_V * L_SEQ];      // raw correlation sums (not yet /512)
__device__ int   g_idx[N_V * TOPK];
__device__ float g_prob[N_B * N_V * TOPK];

// Packed fp32x2 FMA (Blackwell FFMA2) — 2x fp32 MAC throughput
__device__ __forceinline__ unsigned long long ffma2(unsigned long long a,
                                                    unsigned long long b,
                                                    unsigned long long c) {
    unsigned long long d;
    asm("fma.rn.f32x2 %0, %1, %2, %3;" : "=l"(d) : "l"(a), "l"(b), "l"(c));
    return d;
}

// ---------------------------------------------------------------------------
// Phase A: mean correlation sums.
// One CTA per (b,v). Thread (lg, cp) owns lags [8*lg, 8*lg+7] on channel pair cp
// of the current 32-channel chunk. k is staged duplicated (k2[i] = k[i%96]) so
// the circular wrap becomes a linear index. Rolling 8-register window over k.
// ---------------------------------------------------------------------------
__global__ __launch_bounds__(TPB_A) void corr_kernel(const float* __restrict__ q,
                                                     const float* __restrict__ k) {
    __shared__ unsigned long long sq [L_SEQ * 16];
    __shared__ unsigned long long sk2[2 * L_SEQ * 16];
    __shared__ float red[L_SEQ * 16];

    const int tid = threadIdx.x;
    const int bv  = blockIdx.x;
    const int b = bv / N_V, v = bv % N_V;
    const int lg = tid >> 4;           // 0..11
    const int cp = tid & 15;           // channel pair in chunk
    const int base = L_SEQ - 8 * lg;   // k2 index offset: k2[t+base-j] = k[(t-(8lg+j))%96]

    unsigned long long acc[8];
#pragma unroll
    for (int j = 0; j < 8; ++j) acc[j] = 0ull;

    const size_t row0 = ((size_t)b * L_SEQ * N_V + v) * N_C;
    const size_t rstr = (size_t)N_V * N_C;

    for (int ch = 0; ch < N_CHUNK; ++ch) {
        const int c0 = ch * CHUNK_C;
        for (int i = tid; i < L_SEQ * 16; i += TPB_A) {
            const int t = i >> 4, c2 = i & 15;
            const size_t off = row0 + (size_t)t * rstr + c0 + 2 * c2;
            const unsigned long long qv = *reinterpret_cast<const unsigned long long*>(q + off);
            const unsigned long long kv = *reinterpret_cast<const unsigned long long*>(k + off);
            sq[i] = qv;
            sk2[i] = kv;
            sk2[i + L_SEQ * 16] = kv;
        }
        __syncthreads();

        // rolling window: slot s preloaded with k2[base-8+s] for s=1..7
        unsigned long long w[8];
#pragma unroll
        for (int s = 1; s < 8; ++s) w[s] = sk2[(base - 8 + s) * 16 + cp];
        const unsigned long long* kp = sk2 + base * 16 + cp;
        const unsigned long long* qp = sq + cp;
        for (int tb = 0; tb < L_SEQ; tb += 8) {
#pragma unroll
            for (int p = 0; p < 8; ++p) {
                w[p] = kp[(tb + p) * 16];                 // newest: k2[t+base]
                const unsigned long long qv = qp[(tb + p) * 16];
#pragma unroll
                for (int j = 0; j < 8; ++j)
                    acc[j] = ffma2(qv, w[(p - j) & 7], acc[j]);   // lag 8*lg+j
            }
        }
        __syncthreads();
    }

#pragma unroll
    for (int j = 0; j < 8; ++j) {
        const float lo = __uint_as_float((unsigned)(acc[j] & 0xffffffffull));
        const float hi = __uint_as_float((unsigned)(acc[j] >> 32));
        red[(lg * 8 + j) * 16 + cp] = lo + hi;
    }
    __syncthreads();
    if (tid < L_SEQ) {
        float s = 0.f;
#pragma unroll
        for (int i = 0; i < 16; ++i) s += red[tid * 16 + i];
        g_mv[(size_t)bv * L_SEQ + tid] = s;
    }
}

// ---------------------------------------------------------------------------
// Phase B: global mean over b, top-4 per v (ties -> lowest index, matching
// lax.top_k), softmax of gathered mean_values per (b,v). Tiny.
// ---------------------------------------------------------------------------
__global__ void topk_kernel() {
    const int v = blockIdx.x;
    __shared__ float gm[L_SEQ];
    __shared__ int ids[TOPK];
    const int tid = threadIdx.x;
    if (tid < L_SEQ) {
        float s = 0.f;
        for (int b = 0; b < N_B; ++b) s += g_mv[(b * N_V + v) * L_SEQ + tid];
        gm[tid] = s;
    }
    __syncthreads();
    if (tid == 0) {
        for (int kk = 0; kk < TOPK; ++kk) {
            float best = -3.0e38f; int bi = 0;
            for (int l = 0; l < L_SEQ; ++l)
                if (gm[l] > best) { best = gm[l]; bi = l; }
            ids[kk] = bi;
            gm[bi] = -3.0e38f;
            g_idx[v * TOPK + kk] = bi;
        }
    }
    __syncthreads();
    if (tid < N_B) {
        const int b = tid;
        float w[TOPK];
        float mx = -3.0e38f;
        for (int kk = 0; kk < TOPK; ++kk) {
            w[kk] = g_mv[(b * N_V + v) * L_SEQ + ids[kk]] * (1.0f / 512.0f);
            mx = fmaxf(mx, w[kk]);
        }
        float se = 0.f;
        for (int kk = 0; kk < TOPK; ++kk) { w[kk] = expf(w[kk] - mx); se += w[kk]; }
        const float inv = 1.0f / se;
        for (int kk = 0; kk < TOPK; ++kk)
            g_prob[(b * N_V + v) * TOPK + kk] = w[kk] * inv;
    }
}

// ---------------------------------------------------------------------------
// Phase C: out[b,l,v,e,h] = sum_kk p * val[b,(l+idx_kk)%96,v,h,e].
// One CTA per (b,v); l processed in tiles of 4. Gather reads are coalesced
// float4 in input channel order; an (h,e)->(e,h) transpose goes through
// padded smem (stride 68: bank = (4h+e)%32, conflict-free on the read side);
// stores are coalesced float4 in output channel order.
// ---------------------------------------------------------------------------
#define TPB_G 512
#define LT 4

__global__ __launch_bounds__(TPB_G) void agg_kernel(const float* __restrict__ val,
                                                    float* __restrict__ out) {
    __shared__ float s[LT][8 * 68];
    const int bv = blockIdx.x;
    const int b = bv / N_V, v = bv % N_V;

    int idx[TOPK]; float p[TOPK];
#pragma unroll
    for (int kk = 0; kk < TOPK; ++kk) {
        idx[kk] = g_idx[v * TOPK + kk];
        p[kk]   = g_prob[(b * N_V + v) * TOPK + kk];
    }
    const size_t base = ((size_t)b * L_SEQ * N_V + v) * N_C;
    const size_t rstr = (size_t)N_V * N_C;
    const int tid = threadIdx.x;
    const int ls  = tid >> 7;          // l within tile (0..3)
    const int q4  = tid & 127;         // float4 index within 512 channels

    for (int l0 = 0; l0 < L_SEQ; l0 += LT) {
        const int l = l0 + ls;
        int t[TOPK];
#pragma unroll
        for (int kk = 0; kk < TOPK; ++kk) {
            t[kk] = l + idx[kk];
            if (t[kk] >= L_SEQ) t[kk] -= L_SEQ;
        }
        float4 r = make_float4(0.f, 0.f, 0.f, 0.f);
#pragma unroll
        for (int kk = 0; kk < TOPK; ++kk) {
            const float4 x = *reinterpret_cast<const float4*>(
                val + base + (size_t)t[kk] * rstr + 4 * q4);
            r.x += p[kk] * x.x; r.y += p[kk] * x.y;
            r.z += p[kk] * x.z; r.w += p[kk] * x.w;
        }
        // c_in = 4*q4+i = h*64+e  -> staged at s[h*68+e]
        const int h  = q4 >> 4;
        const int e0 = (q4 & 15) * 4;
        s[ls][h * 68 + e0 + 0] = r.x;
        s[ls][h * 68 + e0 + 1] = r.y;
        s[ls][h * 68 + e0 + 2] = r.z;
        s[ls][h * 68 + e0 + 3] = r.w;
        __syncthreads();
        // output channel co = e*8+h : read s[(co&7)*68 + (co>>3)]
        float4 o;
        const int co0 = 4 * q4;
        o.x = s[ls][((co0 + 0) & 7) * 68 + ((co0 + 0) >> 3)];
        o.y = s[ls][((co0 + 1) & 7) * 68 + ((co0 + 1) >> 3)];
        o.z = s[ls][((co0 + 2) & 7) * 68 + ((co0 + 2) >> 3)];
        o.w = s[ls][((co0 + 3) & 7) * 68 + ((co0 + 3) >> 3)];
        *reinterpret_cast<float4*>(out + base + (size_t)l * rstr + co0) = o;
        __syncthreads();
    }
}

extern "C" void kernel_launch(void* const* d_in, const int* in_sizes, int n_in,
                              void* d_out, int out_size) {
    const float* q  = (const float*)d_in[0];
    const float* k  = (const float*)d_in[1];
    const float* vv = (const float*)d_in[2];
    float* out = (float*)d_out;

    corr_kernel<<<N_B * N_V, TPB_A>>>(q, k);
    topk_kernel<<<N_V, 128>>>();
    agg_kernel<<<N_B * N_V, TPB_G>>>(vv, out);
}

// round 2
// speedup vs baseline: 1.0637x; 1.0637x over previous
#include <cuda_runtime.h>

#define L_SEQ 96
#define N_V   207
#define N_B   4
#define N_C   512          // H*E channels
#define TOPK  4
#define CHUNK_C 32         // channels per smem chunk (16 float2 pairs)
#define N_CHUNK (N_C / CHUNK_C)   // 16
#define TPB_A 192          // 12 lag-groups * 16 channel-pairs

// scratch (device globals: no allocation allowed)
__device__ float g_mv[N_B * N_V * L_SEQ];      // raw correlation sums (not yet /512)
__device__ int   g_idx[N_V * TOPK];
__device__ float g_prob[N_B * N_V * TOPK];

// Packed fp32x2 FMA (Blackwell FFMA2) — 2x fp32 MAC throughput
__device__ __forceinline__ unsigned long long ffma2(unsigned long long a,
                                                    unsigned long long b,
                                                    unsigned long long c) {
    unsigned long long d;
    asm("fma.rn.f32x2 %0, %1, %2, %3;" : "=l"(d) : "l"(a), "l"(b), "l"(c));
    return d;
}

// ---------------------------------------------------------------------------
// Phase A: mean correlation sums.
// One CTA per (b,v). Thread (lg, cp) owns lags [8*lg, 8*lg+7] on channel pair
// cp of the current 32-channel chunk. k is staged duplicated (k2[i] = k[i%96])
// so the circular wrap is linear. Rolling 8-register k window, with k/q LDS
// software-pipelined one t-step ahead (hides the 29-cyc LDS latency).
// smem: red aliased onto sq + padded rows -> 36.3KB -> 6 CTAs/SM -> one wave.
// ---------------------------------------------------------------------------
#define SQ_N   (L_SEQ * 16 + 16)        // +1 row pad for prefetch overrun
#define SK2_N  (2 * L_SEQ * 16 + 16)

__global__ __launch_bounds__(TPB_A, 6) void corr_kernel(const float* __restrict__ q,
                                                        const float* __restrict__ k) {
    __shared__ unsigned long long sq [SQ_N];
    __shared__ unsigned long long sk2[SK2_N];

    const int tid = threadIdx.x;
    const int bv  = blockIdx.x;
    const int b = bv / N_V, v = bv % N_V;
    const int lg = tid >> 4;           // 0..11
    const int cp = tid & 15;           // channel pair in chunk
    const int base = L_SEQ - 8 * lg;   // k2 index offset: k2[t+base-j] = k[(t-(8lg+j))%96]

    unsigned long long acc[8];
#pragma unroll
    for (int j = 0; j < 8; ++j) acc[j] = 0ull;

    const size_t row0 = ((size_t)b * L_SEQ * N_V + v) * N_C;
    const size_t rstr = (size_t)N_V * N_C;

    for (int ch = 0; ch < N_CHUNK; ++ch) {
        const int c0 = ch * CHUNK_C;
#pragma unroll
        for (int it = 0; it < (L_SEQ * 16) / TPB_A; ++it) {
            const int i = tid + it * TPB_A;
            const int t = i >> 4, c2 = i & 15;
            const size_t off = row0 + (size_t)t * rstr + c0 + 2 * c2;
            const unsigned long long qv = *reinterpret_cast<const unsigned long long*>(q + off);
            const unsigned long long kv = *reinterpret_cast<const unsigned long long*>(k + off);
            sq[i] = qv;
            sk2[i] = kv;
            sk2[i + L_SEQ * 16] = kv;
        }
        __syncthreads();

        // rolling window: slot s preloaded with k2[base-8+s] for s=1..7
        unsigned long long w[8];
#pragma unroll
        for (int s = 1; s < 8; ++s) w[s] = sk2[(base - 8 + s) * 16 + cp];
        const unsigned long long* kp = sk2 + base * 16 + cp;
        const unsigned long long* qp = sq + cp;

        unsigned long long kv_n = kp[0];
        unsigned long long qv_n = qp[0];
        for (int tb = 0; tb < L_SEQ; tb += 8) {
#pragma unroll
            for (int p = 0; p < 8; ++p) {
                const unsigned long long qv = qv_n;
                w[p] = kv_n;                               // newest: k2[t+base]
                const int tn = tb + p + 1;                 // may hit padded row 96
                kv_n = kp[tn * 16];
                qv_n = qp[tn * 16];
#pragma unroll
                for (int j = 0; j < 8; ++j)
                    acc[j] = ffma2(qv, w[(p - j) & 7], acc[j]);   // lag 8*lg+j
            }
        }
        __syncthreads();
    }

    // reduce across the 16 channel pairs; reuse sq storage as float scratch
    float* red = reinterpret_cast<float*>(sq);
#pragma unroll
    for (int j = 0; j < 8; ++j) {
        const float lo = __uint_as_float((unsigned)(acc[j] & 0xffffffffull));
        const float hi = __uint_as_float((unsigned)(acc[j] >> 32));
        red[(lg * 8 + j) * 16 + cp] = lo + hi;
    }
    __syncthreads();
    if (tid < L_SEQ) {
        float s = 0.f;
#pragma unroll
        for (int i = 0; i < 16; ++i) s += red[tid * 16 + i];
        g_mv[(size_t)bv * L_SEQ + tid] = s;
    }
}

// ---------------------------------------------------------------------------
// Phase B: global mean over b, top-4 per v (ties -> lowest index, matching
// lax.top_k), softmax of gathered mean_values per (b,v). Tiny.
// ---------------------------------------------------------------------------
__global__ void topk_kernel() {
    const int v = blockIdx.x;
    __shared__ float gm[L_SEQ];
    __shared__ int ids[TOPK];
    const int tid = threadIdx.x;
    if (tid < L_SEQ) {
        float s = 0.f;
        for (int b = 0; b < N_B; ++b) s += g_mv[(b * N_V + v) * L_SEQ + tid];
        gm[tid] = s;
    }
    __syncthreads();
    if (tid == 0) {
        for (int kk = 0; kk < TOPK; ++kk) {
            float best = -3.0e38f; int bi = 0;
            for (int l = 0; l < L_SEQ; ++l)
                if (gm[l] > best) { best = gm[l]; bi = l; }
            ids[kk] = bi;
            gm[bi] = -3.0e38f;
            g_idx[v * TOPK + kk] = bi;
        }
    }
    __syncthreads();
    if (tid < N_B) {
        const int b = tid;
        float w[TOPK];
        float mx = -3.0e38f;
        for (int kk = 0; kk < TOPK; ++kk) {
            w[kk] = g_mv[(b * N_V + v) * L_SEQ + ids[kk]] * (1.0f / 512.0f);
            mx = fmaxf(mx, w[kk]);
        }
        float se = 0.f;
        for (int kk = 0; kk < TOPK; ++kk) { w[kk] = expf(w[kk] - mx); se += w[kk]; }
        const float inv = 1.0f / se;
        for (int kk = 0; kk < TOPK; ++kk)
            g_prob[(b * N_V + v) * TOPK + kk] = w[kk] * inv;
    }
}

// ---------------------------------------------------------------------------
// Phase C: out[b,l,v,e,h] = sum_kk p * val[b,(l+idx_kk)%96,v,h,e].
// Read-once design: one CTA per (b, v, e-octant). The CTA stages its
// 96x64-float val slice (c_in = h*64 + e0 + e', h in [0,8), e' in [0,8))
// into smem once, then produces all 96x64 outputs from smem.
// smem row layout t*96 + h*12 + e' makes the read pattern (warp = 32
// consecutive out channels co=e'*8+h -> addr h*12+e1) conflict-free mod 32.
// DRAM traffic: 326MB total (read-once + write-once) vs 815MB before.
// ---------------------------------------------------------------------------
#define TPB_G 256

__global__ __launch_bounds__(TPB_G) void agg_kernel(const float* __restrict__ val,
                                                    float* __restrict__ out) {
    __shared__ float s[L_SEQ * 96];            // 36,864 B
    const int blk = blockIdx.x;
    const int bv = blk >> 3;
    const int ep = blk & 7;                    // e-octant
    const int b = bv / N_V, v = bv % N_V;
    const int e0 = ep * 8;
    const int tid = threadIdx.x;

    int idx[TOPK]; float p[TOPK];
#pragma unroll
    for (int kk = 0; kk < TOPK; ++kk) {
        idx[kk] = g_idx[v * TOPK + kk];
        p[kk]   = g_prob[(b * N_V + v) * TOPK + kk];
    }
    const size_t base = ((size_t)b * L_SEQ * N_V + v) * N_C;
    const size_t rstr = (size_t)N_V * N_C;

    // stage the slice: 96 t x 8 h x 8 e' floats, as 3072 float2 loads
#pragma unroll
    for (int it = 0; it < 3072 / TPB_G; ++it) {
        const int j = tid + it * TPB_G;
        const int t = j >> 5;
        const int r = j & 31;
        const int h = r >> 2;
        const int e2 = (r & 3) * 2;
        const float2 x = *reinterpret_cast<const float2*>(
            val + base + (size_t)t * rstr + h * 64 + e0 + e2);
        s[t * 96 + h * 12 + e2]     = x.x;
        s[t * 96 + h * 12 + e2 + 1] = x.y;
    }
    __syncthreads();

    const int co = tid & 63;        // local out channel = e'*8 + h
    const int h  = co & 7;
    const int e1 = co >> 3;
    const int lofs = tid >> 6;      // 0..3
    const int sidx = h * 12 + e1;

    for (int l0 = 0; l0 < L_SEQ; l0 += 4) {
        const int l = l0 + lofs;
        float r = 0.f;
#pragma unroll
        for (int kk = 0; kk < TOPK; ++kk) {
            int t = l + idx[kk];
            if (t >= L_SEQ) t -= L_SEQ;
            r += p[kk] * s[t * 96 + sidx];
        }
        out[base + (size_t)l * rstr + e0 * 8 + co] = r;
    }
}

extern "C" void kernel_launch(void* const* d_in, const int* in_sizes, int n_in,
                              void* d_out, int out_size) {
    const float* q  = (const float*)d_in[0];
    const float* k  = (const float*)d_in[1];
    const float* vv = (const float*)d_in[2];
    float* out = (float*)d_out;

    corr_kernel<<<N_B * N_V, TPB_A>>>(q, k);
    topk_kernel<<<N_V, 128>>>();
    agg_kernel<<<N_B * N_V * 8, TPB_G>>>(vv, out);
}

// round 3
// speedup vs baseline: 1.2612x; 1.1856x over previous
#include <cuda_runtime.h>

#define L_SEQ 96
#define N_V   207
#define N_B   4
#define N_C   512          // H*E channels
#define TOPK  4
#define CHUNK_C 32         // channels per smem chunk (16 float2 pairs)
#define N_CHUNK (N_C / CHUNK_C)   // 16
#define TPB_A 128          // 8 lag-groups * 16 channel-pairs (4 warps: SMSP-balanced)
#define JL    12           // lags per thread

// scratch (device globals: no allocation allowed)
__device__ float g_mv[N_B * N_V * L_SEQ];      // raw correlation sums (not yet /512)
__device__ int   g_idx[N_V * TOPK];
__device__ float g_prob[N_B * N_V * TOPK];

// Packed fp32x2 FMA (Blackwell FFMA2) — 2x fp32 MAC throughput
__device__ __forceinline__ unsigned long long ffma2(unsigned long long a,
                                                    unsigned long long b,
                                                    unsigned long long c) {
    unsigned long long d;
    asm("fma.rn.f32x2 %0, %1, %2, %3;" : "=l"(d) : "l"(a), "l"(b), "l"(c));
    return d;
}

// ---------------------------------------------------------------------------
// Phase A: mean correlation sums.
// One CTA per (b,v). Thread (lg, cp) owns lags [12*lg, 12*lg+11] on channel
// pair cp of the current 32-channel chunk. 12 FFMA2 per 2 LDS.64 puts the fma
// pipe (6 cyc/SM/step) above the smem crossbar (4 cyc/step) -> fma-bound.
// k staged duplicated (k2[i]=k[i%96]) so the wrap is linear; rolling 12-reg
// k window; k/q LDS prefetched one t-step ahead.
// ---------------------------------------------------------------------------
#define SQ_N   (L_SEQ * 16 + 16)        // +1 row pad for prefetch overrun
#define SK2_N  (2 * L_SEQ * 16 + 16)

__global__ __launch_bounds__(TPB_A, 6) void corr_kernel(const float* __restrict__ q,
                                                        const float* __restrict__ k) {
    __shared__ unsigned long long sq [SQ_N];
    __shared__ unsigned long long sk2[SK2_N];

    const int tid = threadIdx.x;
    const int bv  = blockIdx.x;
    const int b = bv / N_V, v = bv % N_V;
    const int lg = tid >> 4;           // 0..7
    const int cp = tid & 15;           // channel pair in chunk
    const int base = L_SEQ - JL * lg;  // k2[t+base-j] = k[(t-(12lg+j))%96]

    unsigned long long acc[JL];
#pragma unroll
    for (int j = 0; j < JL; ++j) acc[j] = 0ull;

    const size_t row0 = ((size_t)b * L_SEQ * N_V + v) * N_C;
    const size_t rstr = (size_t)N_V * N_C;

    for (int ch = 0; ch < N_CHUNK; ++ch) {
        const int c0 = ch * CHUNK_C;
        // stage: 96 rows x 8 float4 per row = 768 float4 loads each for q,k
#pragma unroll
        for (int it = 0; it < 768 / TPB_A; ++it) {
            const int i = tid + it * TPB_A;
            const int t = i >> 3, f = i & 7;
            const size_t off = row0 + (size_t)t * rstr + c0 + 4 * f;
            const float4 qv = *reinterpret_cast<const float4*>(q + off);
            const float4 kv = *reinterpret_cast<const float4*>(k + off);
            const unsigned long long* qu = reinterpret_cast<const unsigned long long*>(&qv);
            const unsigned long long* ku = reinterpret_cast<const unsigned long long*>(&kv);
            sq[t * 16 + 2 * f]     = qu[0];
            sq[t * 16 + 2 * f + 1] = qu[1];
            sk2[t * 16 + 2 * f]     = ku[0];
            sk2[t * 16 + 2 * f + 1] = ku[1];
            sk2[(t + L_SEQ) * 16 + 2 * f]     = ku[0];
            sk2[(t + L_SEQ) * 16 + 2 * f + 1] = ku[1];
        }
        __syncthreads();

        // rolling window: slot s preloaded with k2[base-12+s] for s=1..11
        unsigned long long w[JL];
#pragma unroll
        for (int s = 1; s < JL; ++s) w[s] = sk2[(base - JL + s) * 16 + cp];
        const unsigned long long* kp = sk2 + base * 16 + cp;
        const unsigned long long* qp = sq + cp;

        unsigned long long kv_n = kp[0];
        unsigned long long qv_n = qp[0];
        for (int tb = 0; tb < L_SEQ; tb += JL) {
#pragma unroll
            for (int p = 0; p < JL; ++p) {
                const unsigned long long qv = qv_n;
                w[p] = kv_n;                               // newest: k2[t+base]
                const int tn = tb + p + 1;                 // may hit padded row 96
                kv_n = kp[tn * 16];
                qv_n = qp[tn * 16];
#pragma unroll
                for (int j = 0; j < JL; ++j)
                    acc[j] = ffma2(qv, w[(p - j + JL) % JL], acc[j]);  // lag 12lg+j
            }
        }
        __syncthreads();
    }

    // reduce across the 16 channel pairs; reuse sq storage as float scratch
    float* red = reinterpret_cast<float*>(sq);
#pragma unroll
    for (int j = 0; j < JL; ++j) {
        const float lo = __uint_as_float((unsigned)(acc[j] & 0xffffffffull));
        const float hi = __uint_as_float((unsigned)(acc[j] >> 32));
        red[(lg * JL + j) * 16 + cp] = lo + hi;
    }
    __syncthreads();
    if (tid < L_SEQ) {
        float s = 0.f;
#pragma unroll
        for (int i = 0; i < 16; ++i) s += red[tid * 16 + i];
        g_mv[(size_t)bv * L_SEQ + tid] = s;
    }
}

// ---------------------------------------------------------------------------
// Phase B: global mean over b, top-4 per v (ties -> lowest index, matching
// lax.top_k), softmax of gathered mean_values per (b,v). Tiny.
// ---------------------------------------------------------------------------
__global__ void topk_kernel() {
    const int v = blockIdx.x;
    __shared__ float gm[L_SEQ];
    __shared__ int ids[TOPK];
    const int tid = threadIdx.x;
    if (tid < L_SEQ) {
        float s = 0.f;
        for (int b = 0; b < N_B; ++b) s += g_mv[(b * N_V + v) * L_SEQ + tid];
        gm[tid] = s;
    }
    __syncthreads();
    if (tid == 0) {
        for (int kk = 0; kk < TOPK; ++kk) {
            float best = -3.0e38f; int bi = 0;
            for (int l = 0; l < L_SEQ; ++l)
                if (gm[l] > best) { best = gm[l]; bi = l; }
            ids[kk] = bi;
            gm[bi] = -3.0e38f;
            g_idx[v * TOPK + kk] = bi;
        }
    }
    __syncthreads();
    if (tid < N_B) {
        const int b = tid;
        float w[TOPK];
        float mx = -3.0e38f;
        for (int kk = 0; kk < TOPK; ++kk) {
            w[kk] = g_mv[(b * N_V + v) * L_SEQ + ids[kk]] * (1.0f / 512.0f);
            mx = fmaxf(mx, w[kk]);
        }
        float se = 0.f;
        for (int kk = 0; kk < TOPK; ++kk) { w[kk] = expf(w[kk] - mx); se += w[kk]; }
        const float inv = 1.0f / se;
        for (int kk = 0; kk < TOPK; ++kk)
            g_prob[(b * N_V + v) * TOPK + kk] = w[kk] * inv;
    }
}

// ---------------------------------------------------------------------------
// Phase C: out[b,l,v,e,h] = sum_kk p * val[b,(l+idx_kk)%96,v,h,e].
// Read-once, one CTA per (b, v, e-octant). The (h,e)->(e,h) transpose happens
// DURING staging: smem is output-major s[t*64 + co] with co = e'*8+h, so the
// compute pass is pure LDS.128 + FFMA + STG.128, all conflict-free/coalesced.
// ---------------------------------------------------------------------------
#define TPB_G 256

__global__ __launch_bounds__(TPB_G) void agg_kernel(const float* __restrict__ val,
                                                    float* __restrict__ out) {
    __shared__ float s[L_SEQ * 64];            // 24,576 B, output-major
    const int blk = blockIdx.x;
    const int bv = blk >> 3;
    const int ep = blk & 7;                    // e-octant
    const int b = bv / N_V, v = bv % N_V;
    const int e0 = ep * 8;
    const int tid = threadIdx.x;

    int idx[TOPK]; float p[TOPK];
#pragma unroll
    for (int kk = 0; kk < TOPK; ++kk) {
        idx[kk] = g_idx[v * TOPK + kk];
        p[kk]   = g_prob[(b * N_V + v) * TOPK + kk];
    }
    const size_t base = ((size_t)b * L_SEQ * N_V + v) * N_C;
    const size_t rstr = (size_t)N_V * N_C;

    // stage + transpose: 96 t x 8 h x 8 e' floats as 3072 float2 loads
#pragma unroll
    for (int it = 0; it < 3072 / TPB_G; ++it) {
        const int j = tid + it * TPB_G;
        const int t = j >> 5;
        const int r = j & 31;
        const int h = r >> 2;
        const int e2 = (r & 3) * 2;
        const float2 x = *reinterpret_cast<const float2*>(
            val + base + (size_t)t * rstr + h * 64 + e0 + e2);
        s[t * 64 + e2 * 8 + h]       = x.x;     // co = e'*8 + h
        s[t * 64 + (e2 + 1) * 8 + h] = x.y;
    }
    __syncthreads();

    const int co0 = (tid & 15) * 4;  // 4 consecutive out channels
    const int lz  = tid >> 4;        // 0..15

#pragma unroll
    for (int li = 0; li < L_SEQ / 16; ++li) {
        const int l = lz + li * 16;
        float4 r = make_float4(0.f, 0.f, 0.f, 0.f);
#pragma unroll
        for (int kk = 0; kk < TOPK; ++kk) {
            int t = l + idx[kk];
            if (t >= L_SEQ) t -= L_SEQ;
            const float4 x = *reinterpret_cast<const float4*>(&s[t * 64 + co0]);
            r.x += p[kk] * x.x; r.y += p[kk] * x.y;
            r.z += p[kk] * x.z; r.w += p[kk] * x.w;
        }
        *reinterpret_cast<float4*>(out + base + (size_t)l * rstr + e0 * 8 + co0) = r;
    }
}

extern "C" void kernel_launch(void* const* d_in, const int* in_sizes, int n_in,
                              void* d_out, int out_size) {
    const float* q  = (const float*)d_in[0];
    const float* k  = (const float*)d_in[1];
    const float* vv = (const float*)d_in[2];
    float* out = (float*)d_out;

    corr_kernel<<<N_B * N_V, TPB_A>>>(q, k);
    topk_kernel<<<N_V, 128>>>();
    agg_kernel<<<N_B * N_V * 8, TPB_G>>>(vv, out);
}